// round 13
// baseline (speedup 1.0000x reference)
#include <cuda_runtime.h>
#include <cuda_fp16.h>
#include <cstdint>

// ---------------------------------------------------------------------------
// 4D ConvTranspose stride2 K=3^4 as 16 parity-class GEMMs on tensor cores
// (ldmatrix + mma.sync m16n8k16 f16, fp32 accum).
//   D[sp=256, co=64] += X[sp, k]·W[co, k],  k = (tap t, ci),  K = 64*T
// R13: 512 threads / 16 warps, warp tile 32sp x 32co -> 32 warps/SM at
// 2 CTAs/SM (occ 24% -> 48%). R12 profile showed pure latency bind
// (occ 24, issue 17, all pipes < 45%). fp16 single-term (rel_err 2.9e-4).
// Single barrier per tap; stage(t+1) issued right after it.
// ---------------------------------------------------------------------------

#define XM 20736            // 12^4 input spatial points
#define OSB 25000000LL
#define OSC 390625
#define OS1 15625
#define OS2 625
#define OS3 25

// prepped operands
__device__ __align__(16) __half g_w16[81*64*64];   // [kidx][co][ci]
__device__ __align__(16) __half g_x16[4L*XM*64];   // [b][m_lin][ci]

// dynamic SMEM: ping-pong buffers. Rows 128B, XOR-swizzled.
#define SM_A    0            // 2 bufs x 256 rows x 128B = 65536
#define SM_B    65536        // 2 bufs x 64 rows x 128B = 16384
#define SM_OFFS 81920        // u16[16*256] = 8192
#define SM_BIAS 90112        // float[64]
#define SM_KOF  90368        // int[16]
#define SM_DD   90432        // char[16][4]
#define SM_TOTAL 90496

#define SWZ(o) ((o) ^ (((o) >> 3) & 0x70))

// ---------------- fused prep kernel ----------------
// blocks [0, 1296): weight transpose+cast; blocks [1296, 3888): x transpose+cast
__global__ void prep_all(const float* __restrict__ w, const float* __restrict__ x) {
    if (blockIdx.x < 1296) {
        int idx = blockIdx.x * 256 + threadIdx.x;
        if (idx >= 331776) return;                 // 64*64*81
        int ci = idx / 5184;
        int r  = idx - ci * 5184;
        int co = r / 81;
        int k  = r - co * 81;
        g_w16[(k * 64 + co) * 64 + ci] = __float2half(w[idx]);
    } else {
        __shared__ float s[64][33];
        int q = blockIdx.x - 1296;                 // 0..2591
        int b = q / 648, m0 = (q - b * 648) * 32, tid = threadIdx.x;
        for (int i = tid; i < 2048; i += 256) {
            int ci = i >> 5, mm = i & 31;
            s[ci][mm] = x[((size_t)(b * 64 + ci)) * XM + m0 + mm];
        }
        __syncthreads();
        int m = tid >> 3, qq = tid & 7;
        union { __half a[8]; uint4 v; } hv;
        #pragma unroll
        for (int j = 0; j < 8; j++)
            hv.a[j] = __float2half(s[qq * 8 + j][m]);
        *(uint4*)(g_x16 + ((size_t)b * XM + m0 + m) * 64 + qq * 8) = hv.v;
    }
}

// ---------------- ptx helpers ----------------
__device__ __forceinline__ uint32_t smem_u32(const void* p) {
    uint32_t a;
    asm("{ .reg .u64 t; cvta.to.shared.u64 t, %1; cvt.u32.u64 %0, t; }" : "=r"(a) : "l"(p));
    return a;
}
__device__ __forceinline__ void ldsm4(uint32_t r[4], uint32_t addr) {
    asm volatile("ldmatrix.sync.aligned.m8n8.x4.shared.b16 {%0,%1,%2,%3}, [%4];"
                 : "=r"(r[0]), "=r"(r[1]), "=r"(r[2]), "=r"(r[3]) : "r"(addr));
}
__device__ __forceinline__ void mma_f16(float c[4], const uint32_t a[4],
                                        uint32_t b0, uint32_t b1) {
    asm volatile("mma.sync.aligned.m16n8k16.row.col.f32.f16.f16.f32 "
                 "{%0,%1,%2,%3}, {%4,%5,%6,%7}, {%8,%9}, {%0,%1,%2,%3};"
                 : "+f"(c[0]), "+f"(c[1]), "+f"(c[2]), "+f"(c[3])
                 : "r"(a[0]), "r"(a[1]), "r"(a[2]), "r"(a[3]), "r"(b0), "r"(b1));
}
__device__ __forceinline__ void cpa16(uint32_t dst, const void* src, bool pred) {
    int sz = pred ? 16 : 0;
    asm volatile("cp.async.cg.shared.global [%0], [%1], 16, %2;"
                 :: "r"(dst), "l"(src), "r"(sz) : "memory");
}

// ---------------- main kernel ----------------
__global__ __launch_bounds__(512, 2) void ct4d_mma(
    const float* __restrict__ bias, float* __restrict__ out)
{
    extern __shared__ char smem[];
    const int tid = threadIdx.x, lane = tid & 31, wrp = tid >> 5;
    const int ws = wrp >> 1;          // sp block 0..7 (32 rows each)
    const int wc = wrp & 1;           // co block 0..1 (32 cols each)
    const int c = blockIdx.z, b = blockIdx.y, tile = blockIdx.x;
    const int p1 = (c >> 3) & 1, p2 = (c >> 2) & 1, p3 = (c >> 1) & 1, p4 = c & 1;
    const int n1 = 13 - p1, n2 = 13 - p2, n3 = 13 - p3, n4 = 13 - p4;
    const int Ntot = n1 * n2 * n3 * n4;
    if (tile * 256 >= Ntot) return;
    const int lgT = 4 - p1 - p2 - p3 - p4;
    const int T = 1 << lgT;

    const uint32_t sb = smem_u32(smem);
    int*          kof  = (int*)(smem + SM_KOF);
    signed char (*dd)[4] = (signed char(*)[4])(smem + SM_DD);
    uint16_t*     offs = (uint16_t*)(smem + SM_OFFS);
    float*        bs   = (float*)(smem + SM_BIAS);

    if (tid < T) {
        int rem = tid, pp[4] = {p1, p2, p3, p4}, d[4], k[4];
        #pragma unroll
        for (int i = 0; i < 4; i++) {
            if (!pp[i]) { d[i] = rem & 1; rem >>= 1; k[i] = 2 * d[i]; }
            else        { d[i] = 0;                  k[i] = 1; }
        }
        kof[tid] = ((k[0] * 3 + k[1]) * 3 + k[2]) * 3 + k[3];
        dd[tid][0] = d[0]; dd[tid][1] = d[1]; dd[tid][2] = d[2]; dd[tid][3] = d[3];
    }
    if (tid < 64) bs[tid] = bias[tid];
    __syncthreads();

    // gather offsets per (tap, sp row); 0xFFFF = OOB/pad
    if (tid < 256) {
        int g = tile * 256 + tid;
        int valid = g < Ntot, m1 = 0, m2 = 0, m3 = 0, m4 = 0;
        if (valid) { m4 = g % n4; int q = g / n4; m3 = q % n3; q /= n3; m2 = q % n2; m1 = q / n2; }
        for (int t = 0; t < T; t++) {
            int off = 0xFFFF;
            if (valid) {
                int a1 = m1 - dd[t][0], a2 = m2 - dd[t][1], a3 = m3 - dd[t][2], a4 = m4 - dd[t][3];
                if (((unsigned)a1 < 12u) & ((unsigned)a2 < 12u) & ((unsigned)a3 < 12u) & ((unsigned)a4 < 12u))
                    off = ((a1 * 12 + a2) * 12 + a3) * 12 + a4;
            }
            offs[t * 256 + tid] = (uint16_t)off;
        }
    }
    __syncthreads();   // offs visible to all threads before staging

    const __half* xb = g_x16 + (size_t)b * XM * 64;

    auto stage = [&](int t, int bf) {
        // B: 64 co rows x 128B. 512 threads: 8 threads/row x 1 seg each.
        {
            const int kb = kof[t] * 64;
            int r = tid >> 3, seg = tid & 7;
            uint32_t so = bf * 8192 + SWZ(r * 128 + seg * 16);
            cpa16(sb + SM_B + so, g_w16 + (kb + r) * 64 + seg * 8, true);
        }
        // A: 256 sp rows x 128B (8 threads/row, 64 rows/pass, 4 passes)
        {
            const uint16_t* ot = offs + t * 256;
            int q8 = tid & 7, rsub = tid >> 3;
            #pragma unroll
            for (int rb = 0; rb < 256; rb += 64) {
                int r = rb + rsub;
                uint32_t off = ot[r];
                bool ok = off != 0xFFFFu;
                uint32_t so = bf * 32768 + SWZ(r * 128 + q8 * 16);
                cpa16(sb + SM_A + so, xb + (size_t)(ok ? off : 0) * 64 + q8 * 8, ok);
            }
        }
        asm volatile("cp.async.commit_group;" ::: "memory");
    };

    float acc[2][4][4];
    #pragma unroll
    for (int i = 0; i < 2; i++)
        #pragma unroll
        for (int j = 0; j < 4; j++)
            #pragma unroll
            for (int q = 0; q < 4; q++) acc[i][j][q] = 0.f;

    stage(0, 0);

    const int arow_s = lane & 15;
    const int aseg   = ((lane >> 4) & 1) * 16;
    const int brow_s = ((lane >> 4) & 1) * 8 + (lane & 7);
    const int bseg   = ((lane >> 3) & 1) * 16;

    for (int t = 0; t < T; t++) {
        const int bf = t & 1;
        // stage(t) was committed a full tap ago -> latency already hidden.
        asm volatile("cp.async.wait_group 0;" ::: "memory");
        // ONE barrier: (a) stage(t) copies from all threads visible,
        // (b) all warps finished compute(t-1), so buffer bf^1 is reusable.
        __syncthreads();
        if (t + 1 < T) stage(t + 1, bf ^ 1);

        const uint32_t abase = sb + SM_A + bf * 32768;
        const uint32_t bbase = sb + SM_B + bf * 8192;

        #pragma unroll
        for (int kk = 0; kk < 4; kk++) {
            uint32_t Af[2][4];
            const uint32_t acol = kk * 32 + aseg;
            #pragma unroll
            for (int i = 0; i < 2; i++)
                ldsm4(Af[i], abase + SWZ((ws * 32 + i * 16 + arow_s) * 128 + acol));
            #pragma unroll
            for (int jp = 0; jp < 2; jp++) {
                uint32_t Bf[4];
                ldsm4(Bf, bbase + SWZ((wc * 32 + jp * 16 + brow_s) * 128 + kk * 32 + bseg));
                #pragma unroll
                for (int i = 0; i < 2; i++) {
                    mma_f16(acc[i][2 * jp],     Af[i], Bf[0], Bf[1]);
                    mma_f16(acc[i][2 * jp + 1], Af[i], Bf[2], Bf[3]);
                }
            }
        }
    }

    // epilogue: bias, strided scatter into the class sub-grid
    float* ob = out + (size_t)b * OSB;
    const int gbase = tile * 256 + ws * 32 + (lane >> 2);
    #pragma unroll
    for (int i = 0; i < 2; i++) {
        #pragma unroll
        for (int h = 0; h < 2; h++) {
            int g = gbase + i * 16 + h * 8;
            if (g >= Ntot) continue;
            int m4 = g % n4; int q = g / n4;
            int m3 = q % n3; q /= n3;
            int m2 = q % n2; int m1 = q / n2;
            long o = (long)(2 * m1 + p1) * OS1 + (2 * m2 + p2) * OS2 +
                     (2 * m3 + p3) * OS3 + (2 * m4 + p4);
            float* op = ob + o;
            #pragma unroll
            for (int j = 0; j < 4; j++) {
                int co = wc * 32 + j * 8 + (lane & 3) * 2;
                op[(size_t)co * OSC]       = acc[i][j][2 * h]     + bs[co];
                op[(size_t)(co + 1) * OSC] = acc[i][j][2 * h + 1] + bs[co + 1];
            }
        }
    }
}

extern "C" void kernel_launch(void* const* d_in, const int* in_sizes, int n_in,
                              void* d_out, int out_size) {
    const float* x    = (const float*)d_in[0];
    const float* w    = (const float*)d_in[1];
    const float* bias = (const float*)d_in[2];
    float* out = (float*)d_out;

    cudaFuncSetAttribute(ct4d_mma, cudaFuncAttributeMaxDynamicSharedMemorySize, SM_TOTAL);

    prep_all<<<3888, 256>>>(w, x);
    // 112 = ceil(13^4 / 256); smaller classes early-exit surplus tiles.
    ct4d_mma<<<dim3(112, 4, 16), 512, SM_TOTAL>>>(bias, out);
}

// round 15
// speedup vs baseline: 1.0742x; 1.0742x over previous
#include <cuda_runtime.h>
#include <cuda_fp16.h>
#include <cstdint>

// ---------------------------------------------------------------------------
// 4D ConvTranspose stride2 K=3^4 as 16 parity-class GEMMs on tensor cores
// (ldmatrix + mma.sync m16n8k16 f16, fp32 accum).
//   D[sp=128, co=64] += X[sp, k]·W[co, k],  k = (tap t, ci),  K = 64*T
// R14: FOUR-stage cp.async pipeline (wait_group 2 -> stage-t copies landed
// 3 compute-phases ago; empty commit_groups pad when T<4). One barrier per
// tap. CTA tile 128x64, 8 warps of 32x32. fp16 single-term (2.9e-4).
// ---------------------------------------------------------------------------

#define XM 20736            // 12^4 input spatial points
#define OSB 25000000LL
#define OSC 390625
#define OS1 15625
#define OS2 625
#define OS3 25

// prepped operands
__device__ __align__(16) __half g_w16[81*64*64];   // [kidx][co][ci]
__device__ __align__(16) __half g_x16[4L*XM*64];   // [b][m_lin][ci]

// dynamic SMEM: 4-stage ring. Rows 128B, XOR-swizzled.
#define SM_A    0            // 4 bufs x 128 rows x 128B = 65536
#define SM_B    65536        // 4 bufs x 64 rows x 128B = 32768
#define SM_OFFS 98304        // u16[16*128] = 4096
#define SM_BIAS 102400       // float[64]
#define SM_KOF  102656       // int[16]
#define SM_DD   102720       // char[16][4]
#define SM_TOTAL 102784

#define SWZ(o) ((o) ^ (((o) >> 3) & 0x70))

// ---------------- fused prep kernel ----------------
__global__ void prep_all(const float* __restrict__ w, const float* __restrict__ x) {
    if (blockIdx.x < 1296) {
        int idx = blockIdx.x * 256 + threadIdx.x;
        if (idx >= 331776) return;                 // 64*64*81
        int ci = idx / 5184;
        int r  = idx - ci * 5184;
        int co = r / 81;
        int k  = r - co * 81;
        g_w16[(k * 64 + co) * 64 + ci] = __float2half(w[idx]);
    } else {
        __shared__ float s[64][33];
        int q = blockIdx.x - 1296;                 // 0..2591
        int b = q / 648, m0 = (q - b * 648) * 32, tid = threadIdx.x;
        for (int i = tid; i < 2048; i += 256) {
            int ci = i >> 5, mm = i & 31;
            s[ci][mm] = x[((size_t)(b * 64 + ci)) * XM + m0 + mm];
        }
        __syncthreads();
        int m = tid >> 3, qq = tid & 7;
        union { __half a[8]; uint4 v; } hv;
        #pragma unroll
        for (int j = 0; j < 8; j++)
            hv.a[j] = __float2half(s[qq * 8 + j][m]);
        *(uint4*)(g_x16 + ((size_t)b * XM + m0 + m) * 64 + qq * 8) = hv.v;
    }
}

// ---------------- ptx helpers ----------------
__device__ __forceinline__ uint32_t smem_u32(const void* p) {
    uint32_t a;
    asm("{ .reg .u64 t; cvta.to.shared.u64 t, %1; cvt.u32.u64 %0, t; }" : "=r"(a) : "l"(p));
    return a;
}
__device__ __forceinline__ void ldsm4(uint32_t r[4], uint32_t addr) {
    asm volatile("ldmatrix.sync.aligned.m8n8.x4.shared.b16 {%0,%1,%2,%3}, [%4];"
                 : "=r"(r[0]), "=r"(r[1]), "=r"(r[2]), "=r"(r[3]) : "r"(addr));
}
__device__ __forceinline__ void mma_f16(float c[4], const uint32_t a[4],
                                        uint32_t b0, uint32_t b1) {
    asm volatile("mma.sync.aligned.m16n8k16.row.col.f32.f16.f16.f32 "
                 "{%0,%1,%2,%3}, {%4,%5,%6,%7}, {%8,%9}, {%0,%1,%2,%3};"
                 : "+f"(c[0]), "+f"(c[1]), "+f"(c[2]), "+f"(c[3])
                 : "r"(a[0]), "r"(a[1]), "r"(a[2]), "r"(a[3]), "r"(b0), "r"(b1));
}
__device__ __forceinline__ void cpa16(uint32_t dst, const void* src, bool pred) {
    int sz = pred ? 16 : 0;
    asm volatile("cp.async.cg.shared.global [%0], [%1], 16, %2;"
                 :: "r"(dst), "l"(src), "r"(sz) : "memory");
}
__device__ __forceinline__ void commit_group() {
    asm volatile("cp.async.commit_group;" ::: "memory");
}

// ---------------- main kernel ----------------
__global__ __launch_bounds__(256) void ct4d_mma(
    const float* __restrict__ bias, float* __restrict__ out)
{
    extern __shared__ char smem[];
    const int tid = threadIdx.x, lane = tid & 31, wrp = tid >> 5;
    const int ws = wrp >> 1;          // sp block 0..3 (32 rows each)
    const int wc = wrp & 1;           // co block 0..1 (32 cols each)
    const int c = blockIdx.z, b = blockIdx.y, tile = blockIdx.x;
    const int p1 = (c >> 3) & 1, p2 = (c >> 2) & 1, p3 = (c >> 1) & 1, p4 = c & 1;
    const int n1 = 13 - p1, n2 = 13 - p2, n3 = 13 - p3, n4 = 13 - p4;
    const int Ntot = n1 * n2 * n3 * n4;
    if (tile * 128 >= Ntot) return;
    const int lgT = 4 - p1 - p2 - p3 - p4;
    const int T = 1 << lgT;

    const uint32_t sb = smem_u32(smem);
    int*          kof  = (int*)(smem + SM_KOF);
    signed char (*dd)[4] = (signed char(*)[4])(smem + SM_DD);
    uint16_t*     offs = (uint16_t*)(smem + SM_OFFS);
    float*        bs   = (float*)(smem + SM_BIAS);

    if (tid < T) {
        int rem = tid, pp[4] = {p1, p2, p3, p4}, d[4], k[4];
        #pragma unroll
        for (int i = 0; i < 4; i++) {
            if (!pp[i]) { d[i] = rem & 1; rem >>= 1; k[i] = 2 * d[i]; }
            else        { d[i] = 0;                  k[i] = 1; }
        }
        kof[tid] = ((k[0] * 3 + k[1]) * 3 + k[2]) * 3 + k[3];
        dd[tid][0] = d[0]; dd[tid][1] = d[1]; dd[tid][2] = d[2]; dd[tid][3] = d[3];
    }
    if (tid < 64) bs[tid] = bias[tid];
    __syncthreads();

    // gather offsets per (tap, sp row); 0xFFFF = OOB/pad
    if (tid < 128) {
        int g = tile * 128 + tid;
        int valid = g < Ntot, m1 = 0, m2 = 0, m3 = 0, m4 = 0;
        if (valid) { m4 = g % n4; int q = g / n4; m3 = q % n3; q /= n3; m2 = q % n2; m1 = q / n2; }
        for (int t = 0; t < T; t++) {
            int off = 0xFFFF;
            if (valid) {
                int a1 = m1 - dd[t][0], a2 = m2 - dd[t][1], a3 = m3 - dd[t][2], a4 = m4 - dd[t][3];
                if (((unsigned)a1 < 12u) & ((unsigned)a2 < 12u) & ((unsigned)a3 < 12u) & ((unsigned)a4 < 12u))
                    off = ((a1 * 12 + a2) * 12 + a3) * 12 + a4;
            }
            offs[t * 128 + tid] = (uint16_t)off;
        }
    }
    __syncthreads();   // offs visible to all threads before staging

    const __half* xb = g_x16 + (size_t)b * XM * 64;

    // stage one tap into ring slot bf (includes commit).
    auto stage = [&](int t, int bf) {
        // B: 64 co rows x 128B. 256 threads: 8 threads/row, 2 rows-passes.
        {
            const int kb = kof[t] * 64;
            int r = tid >> 3, seg = tid & 7;
            #pragma unroll
            for (int rb = 0; rb < 2; rb++) {
                int rr = r + rb * 32;
                uint32_t so = bf * 8192 + SWZ(rr * 128 + seg * 16);
                cpa16(sb + SM_B + so, g_w16 + (kb + rr) * 64 + seg * 8, true);
            }
        }
        // A: 128 sp rows x 128B (8 threads/row, 32 rows/pass, 4 passes)
        {
            const uint16_t* ot = offs + t * 128;
            int q8 = tid & 7, rsub = tid >> 3;
            #pragma unroll
            for (int rb = 0; rb < 128; rb += 32) {
                int r = rb + rsub;
                uint32_t off = ot[r];
                bool ok = off != 0xFFFFu;
                uint32_t so = bf * 16384 + SWZ(r * 128 + q8 * 16);
                cpa16(sb + SM_A + so, xb + (size_t)(ok ? off : 0) * 64 + q8 * 8, ok);
            }
        }
        commit_group();
    };

    float acc[2][4][4];
    #pragma unroll
    for (int i = 0; i < 2; i++)
        #pragma unroll
        for (int j = 0; j < 4; j++)
            #pragma unroll
            for (int q = 0; q < 4; q++) acc[i][j][q] = 0.f;

    // prologue: always 3 committed groups (empty ones keep the count uniform)
    stage(0, 0);
    if (1 < T) stage(1, 1); else commit_group();
    if (2 < T) stage(2, 2); else commit_group();

    const int arow_s = lane & 15;
    const int aseg   = ((lane >> 4) & 1) * 16;
    const int brow_s = ((lane >> 4) & 1) * 8 + (lane & 7);
    const int bseg   = ((lane >> 3) & 1) * 16;

    for (int t = 0; t < T; t++) {
        const int bf = t & 3;
        // stage(t) was committed 3 taps ago; wait only for it (2 newer remain).
        asm volatile("cp.async.wait_group 2;" ::: "memory");
        // ONE barrier: stage(t) visible to all + compute(t-1) done by all
        // (frees ring slot (t+3)&3 == (t-1)&3 for restaging).
        __syncthreads();
        if (t + 3 < T) stage(t + 3, (t + 3) & 3); else commit_group();

        const uint32_t abase = sb + SM_A + bf * 16384;
        const uint32_t bbase = sb + SM_B + bf * 8192;

        #pragma unroll
        for (int kk = 0; kk < 4; kk++) {
            uint32_t Af[2][4];
            const uint32_t acol = kk * 32 + aseg;
            #pragma unroll
            for (int i = 0; i < 2; i++)
                ldsm4(Af[i], abase + SWZ((ws * 32 + i * 16 + arow_s) * 128 + acol));
            #pragma unroll
            for (int jp = 0; jp < 2; jp++) {
                uint32_t Bf[4];
                ldsm4(Bf, bbase + SWZ((wc * 32 + jp * 16 + brow_s) * 128 + kk * 32 + bseg));
                #pragma unroll
                for (int i = 0; i < 2; i++) {
                    mma_f16(acc[i][2 * jp],     Af[i], Bf[0], Bf[1]);
                    mma_f16(acc[i][2 * jp + 1], Af[i], Bf[2], Bf[3]);
                }
            }
        }
    }

    // epilogue: bias, strided scatter into the class sub-grid
    float* ob = out + (size_t)b * OSB;
    const int gbase = tile * 128 + ws * 32 + (lane >> 2);
    #pragma unroll
    for (int i = 0; i < 2; i++) {
        #pragma unroll
        for (int h = 0; h < 2; h++) {
            int g = gbase + i * 16 + h * 8;
            if (g >= Ntot) continue;
            int m4 = g % n4; int q = g / n4;
            int m3 = q % n3; q /= n3;
            int m2 = q % n2; int m1 = q / n2;
            long o = (long)(2 * m1 + p1) * OS1 + (2 * m2 + p2) * OS2 +
                     (2 * m3 + p3) * OS3 + (2 * m4 + p4);
            float* op = ob + o;
            #pragma unroll
            for (int j = 0; j < 4; j++) {
                int co = wc * 32 + j * 8 + (lane & 3) * 2;
                op[(size_t)co * OSC]       = acc[i][j][2 * h]     + bs[co];
                op[(size_t)(co + 1) * OSC] = acc[i][j][2 * h + 1] + bs[co + 1];
            }
        }
    }
}

extern "C" void kernel_launch(void* const* d_in, const int* in_sizes, int n_in,
                              void* d_out, int out_size) {
    const float* x    = (const float*)d_in[0];
    const float* w    = (const float*)d_in[1];
    const float* bias = (const float*)d_in[2];
    float* out = (float*)d_out;

    cudaFuncSetAttribute(ct4d_mma, cudaFuncAttributeMaxDynamicSharedMemorySize, SM_TOTAL);

    prep_all<<<3888, 256>>>(w, x);
    // 224 = ceil(13^4 / 128); smaller classes early-exit surplus tiles.
    ct4d_mma<<<dim3(224, 4, 16), 256, SM_TOTAL>>>(bias, out);
}

// round 16
// speedup vs baseline: 1.2308x; 1.1458x over previous
#include <cuda_runtime.h>
#include <cuda_fp16.h>
#include <cstdint>

// ---------------------------------------------------------------------------
// 4D ConvTranspose stride2 K=3^4. R15: parity classes PAIRED along dim 4 —
// one CTA computes both p4=0 and p4=1 outputs for the same (m1,m2,m3,m4)
// footprint (two accumulator banks, 3*T123 tap slabs). Epilogue writes
// adjacent output floats (o4=2m4, 2m4+1) -> full DRAM sectors, killing the
// 3.7x RMW write amplification that bound R12-R14 (HBM ~2.8 TB/s constant).
// Tensor path: ldmatrix + mma.sync m16n8k16 f16 fp32-acc (rel_err 2.9e-4).
// 4-stage cp.async ring, one barrier per tap.
// ---------------------------------------------------------------------------

#define XM 20736            // 12^4 input spatial points
#define OSB 25000000LL
#define OSC 390625
#define OS1 15625
#define OS2 625
#define OS3 25

// prepped operands
__device__ __align__(16) __half g_w16[81*64*64];   // [kidx][co][ci]
__device__ __align__(16) __half g_x16[4L*XM*64];   // [b][m_lin][ci]

// dynamic SMEM: 4-stage ring. Rows 128B, XOR-swizzled.
#define SM_A    0            // 4 bufs x 128 rows x 128B = 65536
#define SM_B    65536        // 4 bufs x 64 rows x 128B = 32768
#define SM_OFFS 98304        // u16[24*128] = 6144
#define SM_BIAS 104448       // float[64]
#define SM_KOF  104704       // int[24]
#define SM_DD   104800       // char[24][4]
#define SM_TOTAL 104960

#define SWZ(o) ((o) ^ (((o) >> 3) & 0x70))

// ---------------- fused prep kernel ----------------
__global__ void prep_all(const float* __restrict__ w, const float* __restrict__ x) {
    if (blockIdx.x < 1296) {
        int idx = blockIdx.x * 256 + threadIdx.x;
        if (idx >= 331776) return;                 // 64*64*81
        int ci = idx / 5184;
        int r  = idx - ci * 5184;
        int co = r / 81;
        int k  = r - co * 81;
        g_w16[(k * 64 + co) * 64 + ci] = __float2half(w[idx]);
    } else {
        __shared__ float s[64][33];
        int q = blockIdx.x - 1296;                 // 0..2591
        int b = q / 648, m0 = (q - b * 648) * 32, tid = threadIdx.x;
        for (int i = tid; i < 2048; i += 256) {
            int ci = i >> 5, mm = i & 31;
            s[ci][mm] = x[((size_t)(b * 64 + ci)) * XM + m0 + mm];
        }
        __syncthreads();
        int m = tid >> 3, qq = tid & 7;
        union { __half a[8]; uint4 v; } hv;
        #pragma unroll
        for (int j = 0; j < 8; j++)
            hv.a[j] = __float2half(s[qq * 8 + j][m]);
        *(uint4*)(g_x16 + ((size_t)b * XM + m0 + m) * 64 + qq * 8) = hv.v;
    }
}

// ---------------- ptx helpers ----------------
__device__ __forceinline__ uint32_t smem_u32(const void* p) {
    uint32_t a;
    asm("{ .reg .u64 t; cvta.to.shared.u64 t, %1; cvt.u32.u64 %0, t; }" : "=r"(a) : "l"(p));
    return a;
}
__device__ __forceinline__ void ldsm4(uint32_t r[4], uint32_t addr) {
    asm volatile("ldmatrix.sync.aligned.m8n8.x4.shared.b16 {%0,%1,%2,%3}, [%4];"
                 : "=r"(r[0]), "=r"(r[1]), "=r"(r[2]), "=r"(r[3]) : "r"(addr));
}
__device__ __forceinline__ void mma_f16(float c[4], const uint32_t a[4],
                                        uint32_t b0, uint32_t b1) {
    asm volatile("mma.sync.aligned.m16n8k16.row.col.f32.f16.f16.f32 "
                 "{%0,%1,%2,%3}, {%4,%5,%6,%7}, {%8,%9}, {%0,%1,%2,%3};"
                 : "+f"(c[0]), "+f"(c[1]), "+f"(c[2]), "+f"(c[3])
                 : "r"(a[0]), "r"(a[1]), "r"(a[2]), "r"(a[3]), "r"(b0), "r"(b1));
}
__device__ __forceinline__ void cpa16(uint32_t dst, const void* src, bool pred) {
    int sz = pred ? 16 : 0;
    asm volatile("cp.async.cg.shared.global [%0], [%1], 16, %2;"
                 :: "r"(dst), "l"(src), "r"(sz) : "memory");
}
__device__ __forceinline__ void commit_group() {
    asm volatile("cp.async.commit_group;" ::: "memory");
}

// unrolled mma body on accumulator bank AC
#define MMA_TAP(AC)                                                            \
    {                                                                          \
        _Pragma("unroll")                                                      \
        for (int kk = 0; kk < 4; kk++) {                                       \
            uint32_t Af[2][4];                                                 \
            const uint32_t acol = kk * 32 + aseg;                              \
            _Pragma("unroll")                                                  \
            for (int i = 0; i < 2; i++)                                        \
                ldsm4(Af[i], abase + SWZ((ws * 32 + i * 16 + arow_s) * 128 + acol)); \
            _Pragma("unroll")                                                  \
            for (int jp = 0; jp < 2; jp++) {                                   \
                uint32_t Bf[4];                                                \
                ldsm4(Bf, bbase + SWZ((wc * 32 + jp * 16 + brow_s) * 128 + kk * 32 + bseg)); \
                _Pragma("unroll")                                              \
                for (int i = 0; i < 2; i++) {                                  \
                    mma_f16(AC[i][2 * jp],     Af[i], Bf[0], Bf[1]);           \
                    mma_f16(AC[i][2 * jp + 1], Af[i], Bf[2], Bf[3]);           \
                }                                                              \
            }                                                                  \
        }                                                                      \
    }

// ---------------- main kernel ----------------
__global__ __launch_bounds__(256, 2) void ct4d_mma(
    const float* __restrict__ bias, float* __restrict__ out)
{
    extern __shared__ char smem[];
    const int tid = threadIdx.x, lane = tid & 31, wrp = tid >> 5;
    const int ws = wrp >> 1;          // sp block 0..3 (32 rows each)
    const int wc = wrp & 1;           // co block 0..1 (32 cols each)
    const int c = blockIdx.z, b = blockIdx.y, tile = blockIdx.x;
    const int p1 = (c >> 2) & 1, p2 = (c >> 1) & 1, p3 = c & 1;
    const int n1 = 13 - p1, n2 = 13 - p2, n3 = 13 - p3;
    const int Ntot = n1 * n2 * n3 * 13;      // m4 grid is class-0's (13)
    if (tile * 128 >= Ntot) return;
    const int T123 = 1 << (3 - p1 - p2 - p3);
    const int NT = 3 * T123;                 // tap slabs: (k4=0, k4=2)->acc0, k4=1->acc1

    const uint32_t sb = smem_u32(smem);
    int*          kof  = (int*)(smem + SM_KOF);
    signed char (*dd)[4] = (signed char(*)[4])(smem + SM_DD);
    uint16_t*     offs = (uint16_t*)(smem + SM_OFFS);
    float*        bs   = (float*)(smem + SM_BIAS);

    if (tid < NT) {
        int t123 = tid / 3, j = tid - (tid / 3) * 3;
        int rem = t123, pp[3] = {p1, p2, p3}, d[3], k[3];
        #pragma unroll
        for (int i = 0; i < 3; i++) {
            if (!pp[i]) { d[i] = rem & 1; rem >>= 1; k[i] = 2 * d[i]; }
            else        { d[i] = 0;                  k[i] = 1; }
        }
        int k4 = (j < 2) ? 2 * j : 1;
        int d4 = (j < 2) ? j : 0;
        kof[tid] = ((k[0] * 3 + k[1]) * 3 + k[2]) * 3 + k4;
        dd[tid][0] = d[0]; dd[tid][1] = d[1]; dd[tid][2] = d[2]; dd[tid][3] = d4;
    }
    if (tid < 64) bs[tid] = bias[tid];
    __syncthreads();

    // gather offsets per (tap, sp row); 0xFFFF = OOB/pad
    if (tid < 128) {
        int g = tile * 128 + tid;
        int valid = g < Ntot, m1 = 0, m2 = 0, m3 = 0, m4 = 0;
        if (valid) { m4 = g % 13; int q = g / 13; m3 = q % n3; q /= n3; m2 = q % n2; m1 = q / n2; }
        for (int t = 0; t < NT; t++) {
            int off = 0xFFFF;
            if (valid) {
                int a1 = m1 - dd[t][0], a2 = m2 - dd[t][1], a3 = m3 - dd[t][2], a4 = m4 - dd[t][3];
                if (((unsigned)a1 < 12u) & ((unsigned)a2 < 12u) & ((unsigned)a3 < 12u) & ((unsigned)a4 < 12u))
                    off = ((a1 * 12 + a2) * 12 + a3) * 12 + a4;
            }
            offs[t * 128 + tid] = (uint16_t)off;
        }
    }
    __syncthreads();   // offs visible to all threads before staging

    const __half* xb = g_x16 + (size_t)b * XM * 64;

    auto stage = [&](int t, int bf) {
        // B: 64 co rows x 128B. 256 threads: 8 threads/row, 2 row-passes.
        {
            const int kb = kof[t] * 64;
            int r = tid >> 3, seg = tid & 7;
            #pragma unroll
            for (int rb = 0; rb < 2; rb++) {
                int rr = r + rb * 32;
                uint32_t so = bf * 8192 + SWZ(rr * 128 + seg * 16);
                cpa16(sb + SM_B + so, g_w16 + (kb + rr) * 64 + seg * 8, true);
            }
        }
        // A: 128 sp rows x 128B (8 threads/row, 32 rows/pass, 4 passes)
        {
            const uint16_t* ot = offs + t * 128;
            int q8 = tid & 7, rsub = tid >> 3;
            #pragma unroll
            for (int rb = 0; rb < 128; rb += 32) {
                int r = rb + rsub;
                uint32_t off = ot[r];
                bool ok = off != 0xFFFFu;
                uint32_t so = bf * 16384 + SWZ(r * 128 + q8 * 16);
                cpa16(sb + SM_A + so, xb + (size_t)(ok ? off : 0) * 64 + q8 * 8, ok);
            }
        }
        commit_group();
    };

    float acc0[2][4][4], acc1[2][4][4];
    #pragma unroll
    for (int i = 0; i < 2; i++)
        #pragma unroll
        for (int j = 0; j < 4; j++)
            #pragma unroll
            for (int q = 0; q < 4; q++) { acc0[i][j][q] = 0.f; acc1[i][j][q] = 0.f; }

    // prologue: NT >= 3 always, so 3 real stages
    stage(0, 0);
    stage(1, 1);
    stage(2, 2);

    const int arow_s = lane & 15;
    const int aseg   = ((lane >> 4) & 1) * 16;
    const int brow_s = ((lane >> 4) & 1) * 8 + (lane & 7);
    const int bseg   = ((lane >> 3) & 1) * 16;

    for (int t = 0; t < NT; t++) {
        const int bf = t & 3;
        asm volatile("cp.async.wait_group 2;" ::: "memory");   // stage(t) done
        __syncthreads();   // stage(t) visible + compute(t-1) done -> slot free
        if (t + 3 < NT) stage(t + 3, (t + 3) & 3); else commit_group();

        const uint32_t abase = sb + SM_A + bf * 16384;
        const uint32_t bbase = sb + SM_B + bf * 8192;

        if (t - (t / 3) * 3 == 2) {   // k4=1 tap -> odd-parity accumulator
            MMA_TAP(acc1)
        } else {                       // k4 in {0,2} -> even-parity accumulator
            MMA_TAP(acc0)
        }
    }

    // epilogue: both parities per point -> adjacent floats -> full sectors
    float* ob = out + (size_t)b * OSB;
    const int gbase = tile * 128 + ws * 32 + (lane >> 2);
    #pragma unroll
    for (int i = 0; i < 2; i++) {
        #pragma unroll
        for (int h = 0; h < 2; h++) {
            int g = gbase + i * 16 + h * 8;
            if (g >= Ntot) continue;
            int m4 = g % 13; int q = g / 13;
            int m3 = q % n3; q /= n3;
            int m2 = q % n2; int m1 = q / n2;
            long o = (long)(2 * m1 + p1) * OS1 + (2 * m2 + p2) * OS2 +
                     (2 * m3 + p3) * OS3 + 2 * m4;
            float* op = ob + o;
            bool odd_ok = m4 < 12;     // class-1 grid is 12 along m4
            #pragma unroll
            for (int j = 0; j < 4; j++) {
                int co = wc * 32 + j * 8 + (lane & 3) * 2;
                float b0 = bs[co], b1 = bs[co + 1];
                op[(size_t)co * OSC]           = acc0[i][j][2 * h]     + b0;
                op[(size_t)(co + 1) * OSC]     = acc0[i][j][2 * h + 1] + b1;
                if (odd_ok) {
                    op[(size_t)co * OSC + 1]       = acc1[i][j][2 * h]     + b0;
                    op[(size_t)(co + 1) * OSC + 1] = acc1[i][j][2 * h + 1] + b1;
                }
            }
        }
    }
}

extern "C" void kernel_launch(void* const* d_in, const int* in_sizes, int n_in,
                              void* d_out, int out_size) {
    const float* x    = (const float*)d_in[0];
    const float* w    = (const float*)d_in[1];
    const float* bias = (const float*)d_in[2];
    float* out = (float*)d_out;

    cudaFuncSetAttribute(ct4d_mma, cudaFuncAttributeMaxDynamicSharedMemorySize, SM_TOTAL);

    prep_all<<<3888, 256>>>(w, x);
    // 224 = ceil(13^3*13 / 128); z = 8 paired classes (p1,p2,p3).
    ct4d_mma<<<dim3(224, 4, 8), 256, SM_TOTAL>>>(bias, out);
}